// round 16
// baseline (speedup 1.0000x reference)
#include <cuda_runtime.h>
#include <math.h>

#define I_SIZE 256
#define N_NEURONS 1024
#define N_DIMS 64
#define D_FEAT 128
#define T_STEPS 256   // = O_SIZE, only first 256 scan steps are observable
#define W_ELEMS (D_FEAT * D_FEAT)
#define STEPS_PER_CTA 2
#define N_CHAIN_CTAS (T_STEPS / STEPS_PER_CTA)   // 128
#define CLUSTER_N 8                               // CTAs per cluster (16 steps)
#define VPAD 36                                   // padded chunk stride (floats)
#define SENT_U 0x7FC0DEADu   // specific quiet-NaN payload; no finite-math
                             // result in this net can produce it

// Global v handoff slots (used only at cluster boundaries). Data-as-flag:
// each float is its own readiness indicator; init_kernel re-poisons every
// replay.
__device__ float g_v[(T_STEPS + 1) * D_FEAT];

// Fast tanh for the chain: (e^{2x}-1)/(e^{2x}+1), abs err ~1e-6 (feedback-safe).
__device__ __forceinline__ float ftanh(float x)
{
    float xc = fminf(fmaxf(x, -15.f), 15.f);
    float e  = __expf(2.f * xc);
    return __fdividef(e - 1.f, e + 1.f);
}

// MUFU tanh for the output layer only (no feedback; single instruction).
__device__ __forceinline__ float tanh_mufu(float x)
{
    float y;
    asm("tanh.approx.f32 %0, %1;" : "=f"(y) : "f"(x));
    return y;
}

__device__ __forceinline__ unsigned int smem_u32(const void* p)
{
    unsigned int a;
    asm("{ .reg .u64 t; cvta.to.shared.u64 t, %1; cvt.u32.u64 %0, t; }"
        : "=r"(a) : "l"(p));
    return a;
}

// ---------------------------------------------------------------------------
// Init kernel (stream-ordered before chain_kernel each replay):
//   CTA 0      : v_0 = s0 * u -> g_v[0]
//   CTAs 1..64 : poison g_v[1..256] with the sentinel.
// ---------------------------------------------------------------------------
__global__ __launch_bounds__(512) void init_kernel(
    const float* __restrict__ x, const float* __restrict__ pos_head,
    const float* __restrict__ pos_tail)
{
    const int tid = threadIdx.x;

    if (blockIdx.x > 0) {
        const int idx = ((int)blockIdx.x - 1) * 512 + tid;   // 0..32767
        g_v[D_FEAT + idx] = __uint_as_float(SENT_U);
        return;
    }

    __shared__ float sh_T[N_DIMS];
    __shared__ float sh_p[4 * D_FEAT];
    __shared__ float sh_s0;

    if (tid < N_DIMS) {
        float s = 0.f;
        #pragma unroll 4
        for (int k = 0; k < I_SIZE; k++) s += pos_tail[k * N_DIMS + tid];
        sh_T[tid] = s;
    }
    __syncthreads();
    if (tid < 32) {
        float p = sh_T[tid] * pos_head[tid] + sh_T[tid + 32] * pos_head[tid + 32];
        #pragma unroll
        for (int off = 16; off > 0; off >>= 1)
            p += __shfl_xor_sync(0xffffffffu, p, off);
        if (tid == 0) sh_s0 = p;
    }
    {
        const int g = tid >> 7, j = tid & (D_FEAT - 1);
        float u = 0.f;
        #pragma unroll 4
        for (int i = g * 64; i < g * 64 + 64; i++) u += x[i * D_FEAT + j];
        sh_p[g * D_FEAT + j] = u;
    }
    __syncthreads();
    if (tid < D_FEAT) {
        const float u = (sh_p[tid] + sh_p[D_FEAT + tid]) +
                        (sh_p[2 * D_FEAT + tid] + sh_p[3 * D_FEAT + tid]);
        g_v[tid] = sh_s0 * u;   // deterministic fixed-order sums
    }
}

// One step's dot-product contribution for column j, k-chunk ks:
// reads v chunk (bank-conflict-free padded layout), 32 FMAs into 4 accs,
// then a 2-shfl quad reduction. Returns full w[j] in ALL 4 quad lanes.
__device__ __forceinline__ float step_dot(
    const float (&Wc)[32], const float* sh_vp, int ks)
{
    const float4* vb = (const float4*)&sh_vp[ks * VPAD];
    float a0 = 0.f, a1 = 0.f, a2 = 0.f, a3 = 0.f;
    #pragma unroll
    for (int i = 0; i < 8; i++) {
        const float4 v = vb[i];
        a0 = fmaf(v.x, Wc[4 * i + 0], a0);
        a1 = fmaf(v.y, Wc[4 * i + 1], a1);
        a2 = fmaf(v.z, Wc[4 * i + 2], a2);
        a3 = fmaf(v.w, Wc[4 * i + 3], a3);
    }
    float s = (a0 + a1) + (a2 + a3);
    s += __shfl_xor_sync(0xffffffffu, s, 1);   // sum over ks pairs
    s += __shfl_xor_sync(0xffffffffu, s, 2);
    return s;
}

// ---------------------------------------------------------------------------
// Chain kernel, clustered. CTA bid owns steps 2*bid, 2*bid+1.
// Thread mapping: tid = j*4 + ks  (j = output column, ks = 32-row k chunk;
// each warp holds 8 complete columns). k-reduction via shfl quad — no smem
// partials, ONE barrier per step. Intra-cluster v handoff via DSMEM
// (remote store + local volatile-LDS poll); cluster boundaries via L2.
// ---------------------------------------------------------------------------
__global__ __launch_bounds__(512, 1) __cluster_dims__(CLUSTER_N, 1, 1)
void chain_kernel(const float* __restrict__ W, const float* __restrict__ a,
                  float* __restrict__ out)
{
    const int bid = (int)blockIdx.x;       // 0..127
    const int t0  = bid * STEPS_PER_CTA;
    const int t1  = t0 + 1;
    const int tid = (int)threadIdx.x;
    const int j   = tid >> 2;   // output column 0..127
    const int ks  = tid & 3;    // k chunk: rows ks*32 .. ks*32+31

    unsigned int rank;
    asm("mov.u32 %0, %%cluster_ctarank;" : "=r"(rank));

    __shared__ __align__(16) float sh_vin[D_FEAT];      // DSMEM inbox
    __shared__ __align__(16) float sh_vp[4 * VPAD];     // padded v (bank-safe)
    __shared__ __align__(16) float sh_w[2][D_FEAT];
    __shared__ __align__(16) float sh_a[2][N_NEURONS];

    // Poison own inbox BEFORE any peer can write (peers write only after
    // receiving their own v, which is gated behind the cluster barrier).
    if (tid < D_FEAT) sh_vin[tid] = __uint_as_float(SENT_U);

    // 1. W columns for both steps -> registers (off critical path).
    // Wc[r] = W[t][ks*32 + r][j]; 4-sector/instr, 100% sector utilization.
    float WrA[32], WrB[32];
    {
        const float* WbA = W + (size_t)t0 * W_ELEMS + (size_t)(ks * 32) * D_FEAT + j;
        const float* WbB = WbA + W_ELEMS;
        #pragma unroll
        for (int r = 0; r < 32; r++) {
            WrA[r] = WbA[(size_t)r * D_FEAT];
            WrB[r] = WbB[(size_t)r * D_FEAT];
        }
    }
    const float alpha0 = a[(size_t)t0 * N_NEURONS + t0 + 1];
    const float alpha1 = a[(size_t)t1 * N_NEURONS + t1 + 1];

    // a-rows for the expansion phase (8 KB)
    for (int i = tid; i < N_NEURONS; i += 512) {
        sh_a[0][i] = __ldcs(a + (size_t)t0 * N_NEURONS + i);
        sh_a[1][i] = __ldcs(a + (size_t)t1 * N_NEURONS + i);
    }

    // Inbox poisoning must be cluster-visible before peers may write.
    asm volatile("barrier.cluster.arrive.aligned;" ::: "memory");
    asm volatile("barrier.cluster.wait.aligned;" ::: "memory");

    // 2. receive v_{t0} into padded buffer
    if (tid < D_FEAT) {
        unsigned int u;
        if (rank == 0) {
            // cluster head: poll global slot (L2)
            const float* src = &g_v[t0 * D_FEAT + tid];
            do {
                asm volatile("ld.relaxed.gpu.b32 %0, [%1];" : "=r"(u) : "l"(src));
            } while (u == SENT_U);
        } else {
            // poll own inbox with a cheap local volatile LDS
            const unsigned int addr = smem_u32(&sh_vin[tid]);
            do {
                asm volatile("ld.volatile.shared.b32 %0, [%1];"
                             : "=r"(u) : "r"(addr));
            } while (u == SENT_U);
        }
        sh_vp[(tid >> 5) * VPAD + (tid & 31)] = __uint_as_float(u);
    }
    __syncthreads();

    // 3a. step A: w0 = v @ W_t0 (shfl reduce, barrier-free), update v
    {
        const float s = step_dot(WrA, sh_vp, ks);
        const float vn = ftanh(alpha0 * s);       // redundant in quad (cheap)
        if (ks == 0) {
            sh_w[0][j] = s;
            sh_vp[(j >> 5) * VPAD + (j & 31)] = vn;
        }
    }
    __syncthreads();

    // 3b. step B: w1 = v @ W_t1; publish v_{t0+2}
    {
        const float s = step_dot(WrB, sh_vp, ks);
        const float vn = ftanh(alpha1 * s);
        if (ks == 0) {
            sh_w[1][j] = s;
            if (rank < CLUSTER_N - 1) {
                // DSMEM handoff to next CTA's inbox (data-as-flag)
                const unsigned int laddr = smem_u32(&sh_vin[j]);
                asm volatile(
                    "{ .reg .b32 ra; mapa.shared::cluster.u32 ra, %0, %1;\n\t"
                    "  st.relaxed.cluster.shared::cluster.b32 [ra], %2; }"
                    :: "r"(laddr), "r"(rank + 1), "r"(__float_as_uint(vn))
                    : "memory");
            } else {
                // cluster boundary: publish through L2 to next cluster head
                asm volatile("st.relaxed.gpu.b32 [%0], %1;"
                             :: "l"(&g_v[(t0 + 2) * D_FEAT + j]),
                                "r"(__float_as_uint(vn)) : "memory");
            }
        }
    }
    __syncthreads();

    // 4. expansion for both steps: out[t, l, j] = tanh(a[t,l] * w_t[j])
    #pragma unroll
    for (int s = 0; s < 2; s++) {
        float* __restrict__ obase = out + (size_t)(t0 + s) * N_NEURONS * D_FEAT;
        const float* __restrict__ arow = sh_a[s];
        const float* __restrict__ wrow = sh_w[s];
        #pragma unroll 4
        for (int it = 0; it < 64; it++) {
            const int item = it * 512 + tid;   // 0..32767 over (l, jq)
            const int ll = item >> 5;          // l (warp-uniform)
            const int q  = item & 31;          // j quad (lane id)
            const float av = arow[ll];
            const float4 wv = *(const float4*)&wrow[4 * q];
            float4 o;
            o.x = tanh_mufu(av * wv.x);
            o.y = tanh_mufu(av * wv.y);
            o.z = tanh_mufu(av * wv.z);
            o.w = tanh_mufu(av * wv.w);
            __stcs((float4*)(obase + (size_t)ll * D_FEAT + 4 * q), o);
        }
    }
}

extern "C" void kernel_launch(void* const* d_in, const int* in_sizes, int n_in,
                              void* d_out, int out_size)
{
    const float* x        = (const float*)d_in[0];   // (256, 128)
    const float* pos_head = (const float*)d_in[1];   // (1024, 64)
    const float* pos_tail = (const float*)d_in[2];   // (1024, 64)
    const float* W        = (const float*)d_in[3];   // (768, 128, 128)
    const float* a        = (const float*)d_in[4];   // (768, 1024)
    float* out            = (float*)d_out;           // (256, 1024, 128)

    init_kernel<<<65, 512>>>(x, pos_head, pos_tail);
    chain_kernel<<<N_CHAIN_CTAS, 512>>>(W, a, out);
}